// round 8
// baseline (speedup 1.0000x reference)
#include <cuda_runtime.h>

// S4D exact diagonal recurrence, R8 = R7 with the reduce bug fixed (each
// 16-mode half of a partial row is 32 floats = 8 float4s; R7 read only 4,
// dropping half the modes -> rel_err 0.53).
//
// Time-decimated f32x2: even/odd timestep streams share w^2 and pack into one
// f32x2 register with zero swizzle overhead. warp = 1 sequence, lane = mode
// (N2=32) -> 4096 warps (R2 occupancy) at ~6.6 warp-instr per seq-step.

constexpr int Hh = 256;
constexpr int N2 = 32;
constexpr int Bb = 16;
constexpr int Ll = 8192;
constexpr int WPB   = 4;            // warps per block
constexpr int TILE  = 32;           // timesteps per tile
constexpr int ITERS = TILE / 2;     // packed iterations per tile
constexpr int RSTR  = 68;           // floats per partial row (64 data + 4 pad)

using u64 = unsigned long long;

__device__ __forceinline__ u64 pack2(float lo, float hi) {
    u64 r;
    asm("mov.b64 %0, {%1, %2};" : "=l"(r) : "f"(lo), "f"(hi));
    return r;
}
__device__ __forceinline__ u64 fma2(u64 a, u64 b, u64 c) {
    u64 d;
    asm("fma.rn.f32x2 %0, %1, %2, %3;" : "=l"(d) : "l"(a), "l"(b), "l"(c));
    return d;
}
__device__ __forceinline__ u64 mul2(u64 a, u64 b) {
    u64 d;
    asm("mul.rn.f32x2 %0, %1, %2;" : "=l"(d) : "l"(a), "l"(b));
    return d;
}
__device__ __forceinline__ u64 add2(u64 a, u64 b) {
    u64 d;
    asm("add.rn.f32x2 %0, %1, %2;" : "=l"(d) : "l"(a), "l"(b));
    return d;
}
__device__ __forceinline__ u64 shfl_xor64(u64 v, int m) {
    const unsigned lo = __shfl_xor_sync(0xffffffffu, (unsigned)(v & 0xffffffffull), m);
    const unsigned hi = __shfl_xor_sync(0xffffffffu, (unsigned)(v >> 32), m);
    return ((u64)hi << 32) | lo;
}

__global__ __launch_bounds__(WPB * 32, 1)
void s4d_r8(const float* __restrict__ u,
            const float* __restrict__ log_dt,
            const float* __restrict__ log_A_real,
            const float* __restrict__ A_imag,
            const float* __restrict__ C,
            const float* __restrict__ D,
            float* __restrict__ y)
{
    __shared__ float usm [WPB][TILE];        // u[base + i]
    __shared__ float ushm[WPB][TILE + 2];    // u[base + i - 1]
    __shared__ float psm [WPB][ITERS][RSTR]; // per-iter packed partials

    const int warp = threadIdx.x >> 5;
    const int lane = threadIdx.x & 31;      // lane = mode n

    const int g = blockIdx.x * WPB + warp;  // g = b*H + h
    const int h = g & (Hh - 1);

    // ---- per-mode parameters ----
    const float dt = expf(log_dt[h]);
    const float d  = D[h];

    const float ar = -expf(log_A_real[h * N2 + lane]);
    const float ai = A_imag[h * N2 + lane];
    const float mag = expf(ar * dt);
    const float wr = mag * cosf(ai * dt);
    const float wi = mag * sinf(ai * dt);
    const float w2r = wr * wr - wi * wi;    // w^2
    const float w2i = 2.0f * wr * wi;

    const float na = ar * ar + ai * ai;
    const float tr = wr - 1.0f, ti = wi;
    const float qr = (tr * ar + ti * ai) / na;
    const float qi = (ti * ar - tr * ai) / na;
    const float cr = C[(h * N2 + lane) * 2 + 0];
    const float ci = C[(h * N2 + lane) * 2 + 1];
    const float Ctr  =  2.0f * (cr * qr - ci * qi);
    const float nCti = -2.0f * (cr * qi + ci * qr);

    const u64 WRs   = pack2(wr,   wr);
    const u64 WIs   = pack2(wi,   wi);
    const u64 W2Rs  = pack2(w2r,  w2r);
    const u64 W2Is  = pack2(w2i,  w2i);
    const u64 NW2Is = pack2(-w2i, -w2i);
    const u64 CTRs  = pack2(Ctr,  Ctr);
    const u64 NCTIs = pack2(nCti, nCti);
    const u64 Ds    = pack2(d, d);

    u64 XR = 0ull;   // (x_even_r, x_odd_r) == (0,0)
    u64 XI = 0ull;

    const float* __restrict__ up = u + (size_t)g * Ll;
    float*       __restrict__ yp = y + (size_t)g * Ll;

    const int r  = lane & 15;   // reduce: output-pair row
    const int hf = lane >> 4;   // reduce: mode half

    float carry = 0.0f;         // u[base - 1]

    for (int base = 0; base < Ll; base += TILE) {
        const float v = up[base + lane];           // coalesced 128B

        // ---- stage u tile (aligned + 1-shifted copies) ----
        usm [warp][lane]     = v;
        ushm[warp][lane + 1] = v;
        if (lane == 0) ushm[warp][0] = carry;
        carry = __shfl_sync(0xffffffffu, v, 31);   // u[base+31] for next tile
        __syncwarp();

        // ---- 16 packed iterations = 32 timesteps ----
        #pragma unroll
        for (int k = 0; k < ITERS; ++k) {
            const u64 Ua = *reinterpret_cast<const u64*>(&ushm[warp][2 * k]);
            const u64 Ub = *reinterpret_cast<const u64*>(&usm [warp][2 * k]);

            const u64 Sr = fma2(WRs, Ua, Ub);      // Re(w*u_prev + u_cur)
            const u64 Si = mul2(WIs, Ua);          // Im(w*u_prev)

            const u64 t1  = fma2(NW2Is, XI, Sr);
            const u64 nXR = fma2(W2Rs,  XR, t1);
            const u64 t2  = fma2(W2Rs,  XI, Si);
            XI = fma2(W2Is, XR, t2);
            XR = nXR;

            const u64 P = fma2(CTRs, XR, mul2(NCTIs, XI));
            *reinterpret_cast<u64*>(&psm[warp][k][2 * lane]) = P;  // STS.64
        }
        __syncwarp();

        // ---- reduce: lane (hf, r) sums its 16-mode half (32 floats) of
        //      output pair (2r, 2r+1), then combines halves via shfl ----
        {
            const float4* p4 =
                reinterpret_cast<const float4*>(&psm[warp][r][hf * 32]);
            u64 acc = 0ull;
            #pragma unroll
            for (int i = 0; i < 8; ++i) {          // 8 x float4 = 32 floats
                const float4 q = p4[i];
                acc = add2(acc, pack2(q.x, q.y));
                acc = add2(acc, pack2(q.z, q.w));
            }
            acc = add2(acc, shfl_xor64(acc, 16));  // combine mode halves
            const u64 U2 = *reinterpret_cast<const u64*>(&usm[warp][2 * r]);
            const u64 out = fma2(Ds, U2, acc);
            if (lane < 16)
                *reinterpret_cast<u64*>(yp + base + 2 * r) = out;  // STG.64
        }
        __syncwarp();   // protect usm/ushm before next tile's staging
    }
}

extern "C" void kernel_launch(void* const* d_in, const int* in_sizes, int n_in,
                              void* d_out, int out_size)
{
    const float* u          = (const float*)d_in[0];
    const float* log_dt     = (const float*)d_in[1];
    const float* log_A_real = (const float*)d_in[2];
    const float* A_imag     = (const float*)d_in[3];
    const float* C          = (const float*)d_in[4];
    const float* D          = (const float*)d_in[5];
    float* y = (float*)d_out;

    const int seqs = Bb * Hh;                // 4096 sequences, 1 per warp
    const int grid = seqs / WPB;             // 1024 blocks of 4 warps
    s4d_r8<<<grid, WPB * 32>>>(u, log_dt, log_A_real, A_imag, C, D, y);
}

// round 9
// speedup vs baseline: 2.5456x; 2.5456x over previous
#include <cuda_runtime.h>
#include <cstdint>
#include <math.h>

// S4D via chunked state-passing + tensor cores (tf32 mma, fp32 accumulate).
//
//   y[64c+i] = sum_{j<=i} k[i-j] u[64c+j]            (Toeplitz GEMM, T @ U)
//            + Re( sum_n Ct_n w_n^{i+1} X_n[c] )     (projection GEMM, PM @ X)
//            + D u[64c+i]
//   X[c+1] = w^64 X[c] + V[c],  V[c] = sum_j w^{63-j} u[64c+j]  (VM @ U + scan)
//
// Param kernel (per h): k[0:64], VM (64x64: rows 0-31 Re(w^{63-i}), 32-63 Im),
// T (Toeplitz of k), PM (PM[i][n]=Re(Ct w^{i+1}), PM[i][32+n]=-Im(Ct w^{i+1})),
// w64. All matrices tf32-rounded (cvt.rna) at write time.
// Main kernel: 1 block per (b,h), 4 warps; u resident in smem; V GEMM ->
// mode-space scan (warp 0) -> Y GEMM fused epilogue (+D*u) -> coalesced-ish STG.

constexpr int Hh = 256;
constexpr int N2 = 32;
constexpr int Bb = 16;
constexpr int Ll = 8192;
constexpr int LC  = 64;     // chunk length
constexpr int NC  = 128;    // chunks per sequence
constexpr int STR = 68;     // smem/global matrix stride (banks: 68%32=4)

// ---- device scratch (static: no allocation) ----
__device__ float g_VM[Hh * 64 * STR];   // [h][vrow][i]
__device__ float g_T [Hh * 64 * STR];   // [h][i][j]
__device__ float g_PM[Hh * 64 * STR];   // [h][i][krow]
__device__ float g_w64r[Hh * N2];
__device__ float g_w64i[Hh * N2];

__device__ __forceinline__ float tf32r(float x) {
    uint32_t u;
    asm("cvt.rna.tf32.f32 %0, %1;" : "=r"(u) : "f"(x));
    return __uint_as_float(u);
}

__device__ __forceinline__ void mma_tf32(float& d0, float& d1, float& d2, float& d3,
                                         const uint32_t a[4], uint32_t b0, uint32_t b1) {
    asm volatile(
        "mma.sync.aligned.m16n8k8.row.col.f32.tf32.tf32.f32 "
        "{%0,%1,%2,%3}, {%4,%5,%6,%7}, {%8,%9}, {%0,%1,%2,%3};"
        : "+f"(d0), "+f"(d1), "+f"(d2), "+f"(d3)
        : "r"(a[0]), "r"(a[1]), "r"(a[2]), "r"(a[3]), "r"(b0), "r"(b1));
}

// ============================ param kernel =============================
__global__ __launch_bounds__(64, 4)
void s4d_param(const float* __restrict__ log_dt,
               const float* __restrict__ log_A_real,
               const float* __restrict__ A_imag,
               const float* __restrict__ C)
{
    const int h = blockIdx.x;
    const int t = threadIdx.x;        // 0..63

    __shared__ float k_s[64];
    __shared__ float ctr_s[N2], cti_s[N2], dar_s[N2], dai_s[N2];

    if (t < N2) {
        const int n = t;
        const float dt = expf(log_dt[h]);
        const float ar = -expf(log_A_real[h * N2 + n]);
        const float ai = A_imag[h * N2 + n];
        const float dtar = ar * dt, dtai = ai * dt;
        const float na = ar * ar + ai * ai;
        const float mag = expf(dtar);
        const float wr = mag * cosf(dtai);
        const float wi = mag * sinf(dtai);
        const float tr = wr - 1.0f, ti = wi;
        const float qr = (tr * ar + ti * ai) / na;
        const float qi = (ti * ar - tr * ai) / na;
        const float cr = C[(h * N2 + n) * 2 + 0];
        const float ci = C[(h * N2 + n) * 2 + 1];
        ctr_s[n] = 2.0f * (cr * qr - ci * qi);
        cti_s[n] = 2.0f * (cr * qi + ci * qr);
        dar_s[n] = dtar;
        dai_s[n] = dtai;
        // w^64
        const float m64 = expf(64.0f * dtar);
        g_w64r[h * N2 + n] = m64 * cosf(64.0f * dtai);
        g_w64i[h * N2 + n] = m64 * sinf(64.0f * dtai);
    }
    __syncthreads();

    // k[m] = Re(sum_n Ct_n w_n^m),  m = t
    {
        float sum = 0.0f;
        const float m = (float)t;
        for (int n = 0; n < N2; ++n) {
            const float e = expf(m * dar_s[n]);
            float sn, cs;
            sincosf(m * dai_s[n], &sn, &cs);
            sum += ctr_s[n] * (e * cs) - cti_s[n] * (e * sn);
        }
        k_s[t] = sum;
    }
    __syncthreads();

    // T[i][j] = k[i-j] (j<=i), tf32-rounded.  thread = row i
    {
        float* Trow = g_T + (h * 64 + t) * STR;
        for (int j = 0; j < 64; ++j)
            Trow[j] = (j <= t) ? tf32r(k_s[t - j]) : 0.0f;
    }

    // VM[vrow][i]: vrow = t; n = t&31; Re for t<32 else Im of w^{63-i}
    {
        const int n = t & 31;
        const bool re = (t < N2);
        float* Vrow = g_VM + (h * 64 + t) * STR;
        for (int i = 0; i < 64; ++i) {
            const float e = (float)(63 - i);
            const float mg = expf(e * dar_s[n]);
            float sn, cs;
            sincosf(e * dai_s[n], &sn, &cs);
            Vrow[i] = tf32r(re ? mg * cs : mg * sn);
        }
    }

    // PM[i][n] = Re(Ct_n w^{i+1}); PM[i][32+n] = -Im(Ct_n w^{i+1}). thread = i
    {
        float* Prow = g_PM + (h * 64 + t) * STR;
        const float p = (float)(t + 1);
        for (int n = 0; n < N2; ++n) {
            const float mg = expf(p * dar_s[n]);
            float sn, cs;
            sincosf(p * dai_s[n], &sn, &cs);
            const float wr = mg * cs, wi = mg * sn;
            const float zr = ctr_s[n] * wr - cti_s[n] * wi;
            const float zi = ctr_s[n] * wi + cti_s[n] * wr;
            Prow[n]      = tf32r(zr);
            Prow[N2 + n] = tf32r(-zi);
        }
    }
}

// ============================= main kernel =============================
__global__ __launch_bounds__(128, 3)
void s4d_main(const float* __restrict__ u,
              const float* __restrict__ Dv,
              float* __restrict__ y)
{
    extern __shared__ float sh[];
    float* u_s  = sh;                 // [NC][STR] : u, tf32-rounded
    float* vx_s = sh + NC * STR;      // [NC][STR] : V then X (rows 0-63)

    const int g = blockIdx.x;         // g = b*H + h
    const int h = g & (Hh - 1);
    const int tid  = threadIdx.x;
    const int warp = tid >> 5;
    const int lane = tid & 31;
    const int gid  = lane >> 2;       // mma group id (0..7)
    const int tig  = lane & 3;        // thread in group (0..3)

    const float* __restrict__ up = u + (size_t)g * Ll;
    float*       __restrict__ yp = y + (size_t)g * Ll;

    // ---- load u into smem (tf32-rounded), layout [c][i] stride 68 ----
    for (int idx = tid; idx < Ll / 4; idx += 128) {
        const float4 v = reinterpret_cast<const float4*>(up)[idx];
        const int l = idx * 4;
        const int c = l >> 6, i = l & 63;
        float4 w;
        w.x = tf32r(v.x); w.y = tf32r(v.y); w.z = tf32r(v.z); w.w = tf32r(v.w);
        *reinterpret_cast<float4*>(&u_s[c * STR + i]) = w;
    }
    __syncthreads();

    // ================= V GEMM: V(64x128) = VM(64x64) @ U(64x128) =========
    {
        uint32_t aV[8][4];
        const float* VMh = g_VM + h * 64 * STR;
        const int r0 = 16 * warp + gid;
        #pragma unroll
        for (int kk = 0; kk < 8; ++kk) {
            const int c0 = kk * 8 + tig;
            aV[kk][0] = __float_as_uint(VMh[r0 * STR + c0]);
            aV[kk][1] = __float_as_uint(VMh[(r0 + 8) * STR + c0]);
            aV[kk][2] = __float_as_uint(VMh[r0 * STR + c0 + 4]);
            aV[kk][3] = __float_as_uint(VMh[(r0 + 8) * STR + c0 + 4]);
        }
        for (int ntg = 0; ntg < 4; ++ntg) {          // 4 ntiles at a time
            float acc[4][4];
            #pragma unroll
            for (int q = 0; q < 4; ++q)
                acc[q][0] = acc[q][1] = acc[q][2] = acc[q][3] = 0.0f;
            #pragma unroll
            for (int kk = 0; kk < 8; ++kk) {
                #pragma unroll
                for (int q = 0; q < 4; ++q) {
                    const int c0 = (ntg * 4 + q) * 8;
                    const uint32_t b0 = __float_as_uint(
                        u_s[(c0 + gid) * STR + kk * 8 + tig]);
                    const uint32_t b1 = __float_as_uint(
                        u_s[(c0 + gid) * STR + kk * 8 + tig + 4]);
                    mma_tf32(acc[q][0], acc[q][1], acc[q][2], acc[q][3],
                             aV[kk], b0, b1);
                }
            }
            #pragma unroll
            for (int q = 0; q < 4; ++q) {
                const int c0 = (ntg * 4 + q) * 8;
                const int cc = c0 + 2 * tig;
                vx_s[cc * STR + r0]           = acc[q][0];
                vx_s[(cc + 1) * STR + r0]     = acc[q][1];
                vx_s[cc * STR + r0 + 8]       = acc[q][2];
                vx_s[(cc + 1) * STR + r0 + 8] = acc[q][3];
            }
        }
    }
    __syncthreads();

    // ================= scan: X[c+1] = w64 X[c] + V[c] (warp 0) ===========
    if (warp == 0) {
        const float w64r = g_w64r[h * N2 + lane];
        const float w64i = g_w64i[h * N2 + lane];
        float xr = 0.0f, xi = 0.0f;
        for (int c = 0; c < NC; ++c) {
            const float vr = vx_s[c * STR + lane];
            const float vi = vx_s[c * STR + N2 + lane];
            vx_s[c * STR + lane]      = tf32r(xr);   // X[c] = state before chunk c
            vx_s[c * STR + N2 + lane] = tf32r(xi);
            const float nxr = fmaf(w64r, xr, fmaf(-w64i, xi, vr));
            xi = fmaf(w64i, xr, fmaf(w64r, xi, vi));
            xr = nxr;
        }
    }
    __syncthreads();

    // ====== Y GEMM: Y = T @ U + PM @ X, epilogue += D*u, store ===========
    {
        uint32_t aY[16][4];
        const float* Th  = g_T  + h * 64 * STR;
        const float* PMh = g_PM + h * 64 * STR;
        const int r0 = 16 * warp + gid;
        #pragma unroll
        for (int kk = 0; kk < 8; ++kk) {
            const int c0 = kk * 8 + tig;
            aY[kk][0] = __float_as_uint(Th[r0 * STR + c0]);
            aY[kk][1] = __float_as_uint(Th[(r0 + 8) * STR + c0]);
            aY[kk][2] = __float_as_uint(Th[r0 * STR + c0 + 4]);
            aY[kk][3] = __float_as_uint(Th[(r0 + 8) * STR + c0 + 4]);
            aY[8 + kk][0] = __float_as_uint(PMh[r0 * STR + c0]);
            aY[8 + kk][1] = __float_as_uint(PMh[(r0 + 8) * STR + c0]);
            aY[8 + kk][2] = __float_as_uint(PMh[r0 * STR + c0 + 4]);
            aY[8 + kk][3] = __float_as_uint(PMh[(r0 + 8) * STR + c0 + 4]);
        }
        const float d = Dv[h];

        for (int ntg = 0; ntg < 4; ++ntg) {
            float acc[4][4];
            #pragma unroll
            for (int q = 0; q < 4; ++q)
                acc[q][0] = acc[q][1] = acc[q][2] = acc[q][3] = 0.0f;
            // K-segment 1: T @ U
            #pragma unroll
            for (int kk = 0; kk < 8; ++kk) {
                #pragma unroll
                for (int q = 0; q < 4; ++q) {
                    const int c0 = (ntg * 4 + q) * 8;
                    const uint32_t b0 = __float_as_uint(
                        u_s[(c0 + gid) * STR + kk * 8 + tig]);
                    const uint32_t b1 = __float_as_uint(
                        u_s[(c0 + gid) * STR + kk * 8 + tig + 4]);
                    mma_tf32(acc[q][0], acc[q][1], acc[q][2], acc[q][3],
                             aY[kk], b0, b1);
                }
            }
            // K-segment 2: PM @ X
            #pragma unroll
            for (int kk = 0; kk < 8; ++kk) {
                #pragma unroll
                for (int q = 0; q < 4; ++q) {
                    const int c0 = (ntg * 4 + q) * 8;
                    const uint32_t b0 = __float_as_uint(
                        vx_s[(c0 + gid) * STR + kk * 8 + tig]);
                    const uint32_t b1 = __float_as_uint(
                        vx_s[(c0 + gid) * STR + kk * 8 + tig + 4]);
                    mma_tf32(acc[q][0], acc[q][1], acc[q][2], acc[q][3],
                             aY[8 + kk], b0, b1);
                }
            }
            // epilogue: + D*u, store (32B-sector coalesced)
            #pragma unroll
            for (int q = 0; q < 4; ++q) {
                const int c0 = (ntg * 4 + q) * 8;
                const int cc = c0 + 2 * tig;
                const int i0 = r0;
                yp[cc * LC + i0] =
                    fmaf(d, u_s[cc * STR + i0], acc[q][0]);
                yp[(cc + 1) * LC + i0] =
                    fmaf(d, u_s[(cc + 1) * STR + i0], acc[q][1]);
                yp[cc * LC + i0 + 8] =
                    fmaf(d, u_s[cc * STR + i0 + 8], acc[q][2]);
                yp[(cc + 1) * LC + i0 + 8] =
                    fmaf(d, u_s[(cc + 1) * STR + i0 + 8], acc[q][3]);
            }
        }
    }
}

// ============================== launch =================================
extern "C" void kernel_launch(void* const* d_in, const int* in_sizes, int n_in,
                              void* d_out, int out_size)
{
    const float* u          = (const float*)d_in[0];
    const float* log_dt     = (const float*)d_in[1];
    const float* log_A_real = (const float*)d_in[2];
    const float* A_imag     = (const float*)d_in[3];
    const float* C          = (const float*)d_in[4];
    const float* D          = (const float*)d_in[5];
    float* y = (float*)d_out;

    const int smem = 2 * NC * STR * (int)sizeof(float);   // 69632 B
    cudaFuncSetAttribute(s4d_main,
                         cudaFuncAttributeMaxDynamicSharedMemorySize, smem);

    s4d_param<<<Hh, 64>>>(log_dt, log_A_real, A_imag, C);
    s4d_main<<<Bb * Hh, 128, smem>>>(u, D, y);
}

// round 10
// speedup vs baseline: 2.8886x; 1.1347x over previous
#include <cuda_runtime.h>
#include <cstdint>
#include <math.h>

// S4D via chunked state-passing + tf32 tensor cores. R10:
//  - 256 threads/block (8 warps): warp = (row-tile mrow=warp&3, n-half=warp>>2)
//  - parallel 8-segment scan (local scan -> warp0 prefix -> correction chain)
//  - Toeplitz A-fragments prefetched before the scan barrier
//  - param kernel writes coalesced (thread = column)

constexpr int Hh = 256;
constexpr int N2 = 32;
constexpr int Bb = 16;
constexpr int Ll = 8192;
constexpr int LC  = 64;     // chunk length
constexpr int NC  = 128;    // chunks per sequence
constexpr int STR = 68;     // matrix row stride (floats)

__device__ float g_VM[Hh * 64 * STR];
__device__ float g_T [Hh * 64 * STR];
__device__ float g_PM[Hh * 64 * STR];
__device__ float g_w64r[Hh * N2];
__device__ float g_w64i[Hh * N2];

__device__ __forceinline__ float tf32r(float x) {
    uint32_t u;
    asm("cvt.rna.tf32.f32 %0, %1;" : "=r"(u) : "f"(x));
    return __uint_as_float(u);
}

__device__ __forceinline__ void mma_tf32(float& d0, float& d1, float& d2, float& d3,
                                         const uint32_t a[4], uint32_t b0, uint32_t b1) {
    asm volatile(
        "mma.sync.aligned.m16n8k8.row.col.f32.tf32.tf32.f32 "
        "{%0,%1,%2,%3}, {%4,%5,%6,%7}, {%8,%9}, {%0,%1,%2,%3};"
        : "+f"(d0), "+f"(d1), "+f"(d2), "+f"(d3)
        : "r"(a[0]), "r"(a[1]), "r"(a[2]), "r"(a[3]), "r"(b0), "r"(b1));
}

// ============================ param kernel =============================
__global__ __launch_bounds__(128, 8)
void s4d_param(const float* __restrict__ log_dt,
               const float* __restrict__ log_A_real,
               const float* __restrict__ A_imag,
               const float* __restrict__ C)
{
    const int h = blockIdx.x;
    const int t = threadIdx.x;          // 0..127

    __shared__ float k_s[64];
    __shared__ float ctr_s[N2], cti_s[N2], dar_s[N2], dai_s[N2];

    if (t < N2) {
        const int n = t;
        const float dt = expf(log_dt[h]);
        const float ar = -expf(log_A_real[h * N2 + n]);
        const float ai = A_imag[h * N2 + n];
        const float dtar = ar * dt, dtai = ai * dt;
        const float na = ar * ar + ai * ai;
        const float mag = expf(dtar);
        const float wr = mag * cosf(dtai);
        const float wi = mag * sinf(dtai);
        const float tr = wr - 1.0f, ti = wi;
        const float qr = (tr * ar + ti * ai) / na;
        const float qi = (ti * ar - tr * ai) / na;
        const float cr = C[(h * N2 + n) * 2 + 0];
        const float ci = C[(h * N2 + n) * 2 + 1];
        ctr_s[n] = 2.0f * (cr * qr - ci * qi);
        cti_s[n] = 2.0f * (cr * qi + ci * qr);
        dar_s[n] = dtar;
        dai_s[n] = dtai;
        const float m64 = expf(64.0f * dtar);
        g_w64r[h * N2 + n] = m64 * cosf(64.0f * dtai);
        g_w64i[h * N2 + n] = m64 * sinf(64.0f * dtai);
    }
    __syncthreads();

    if (t < 64) {                       // k[m] = Re(sum_n Ct_n w_n^m)
        float sum = 0.0f;
        const float m = (float)t;
        for (int n = 0; n < N2; ++n) {
            const float e = expf(m * dar_s[n]);
            float sn, cs;
            sincosf(m * dai_s[n], &sn, &cs);
            sum += ctr_s[n] * (e * cs) - cti_s[n] * (e * sn);
        }
        k_s[t] = sum;
    }
    __syncthreads();

    const int col = t & 63;
    const int ro  = t >> 6;             // 0 or 1: interleave rows

    // T[r][col] = k[r-col] (col<=r), coalesced across col
    for (int r = ro; r < 64; r += 2)
        g_T[(h * 64 + r) * STR + col] =
            (col <= r) ? tf32r(k_s[r - col]) : 0.0f;

    // VM[vr][col] = Re/Im(w_{vr&31}^{63-col})
    for (int vr = ro; vr < 64; vr += 2) {
        const int n = vr & 31;
        const float e = (float)(63 - col);
        const float mg = expf(e * dar_s[n]);
        float sn, cs;
        sincosf(e * dai_s[n], &sn, &cs);
        g_VM[(h * 64 + vr) * STR + col] =
            tf32r((vr < 32) ? mg * cs : mg * sn);
    }

    // PM[i][col]: col<32 -> Re(Ct_n w^{i+1}), col>=32 -> -Im(Ct_n w^{i+1})
    for (int i = ro; i < 64; i += 2) {
        const int n = col & 31;
        const float p = (float)(i + 1);
        const float mg = expf(p * dar_s[n]);
        float sn, cs;
        sincosf(p * dai_s[n], &sn, &cs);
        const float wr = mg * cs, wi = mg * sn;
        const float zr = ctr_s[n] * wr - cti_s[n] * wi;
        const float zi = ctr_s[n] * wi + cti_s[n] * wr;
        g_PM[(h * 64 + i) * STR + col] = tf32r((col < 32) ? zr : -zi);
    }
}

// ============================= main kernel =============================
__global__ __launch_bounds__(256, 2)
void s4d_main(const float* __restrict__ u,
              const float* __restrict__ Dv,
              float* __restrict__ y)
{
    extern __shared__ float sh[];
    float* u_s   = sh;                   // [NC][STR] tf32-rounded u
    float* vx_s  = sh + NC * STR;        // [NC][STR] V then X
    float* seg_s = sh + 2 * NC * STR;    // [8][136]: T(r@0,i@32) P(r@68,i@100)

    const int g = blockIdx.x;            // b*H + h
    const int h = g & (Hh - 1);
    const int tid   = threadIdx.x;
    const int warp  = tid >> 5;
    const int lane  = tid & 31;
    const int gid   = lane >> 2;
    const int tig   = lane & 3;
    const int mrow  = warp & 3;          // row-tile (rows 16*mrow + gid, +8)
    const int nhalf = warp >> 2;         // column half
    const int r0    = 16 * mrow + gid;

    const float* __restrict__ up = u + (size_t)g * Ll;
    float*       __restrict__ yp = y + (size_t)g * Ll;

    // ---- stage u (tf32-rounded) ----
    for (int idx = tid; idx < Ll / 4; idx += 256) {
        const float4 v = reinterpret_cast<const float4*>(up)[idx];
        const int l = idx * 4;
        const int c = l >> 6, i = l & 63;
        float4 w;
        w.x = tf32r(v.x); w.y = tf32r(v.y); w.z = tf32r(v.z); w.w = tf32r(v.w);
        *reinterpret_cast<float4*>(&u_s[c * STR + i]) = w;
    }
    __syncthreads();

    // ================= V GEMM: V = VM @ U (this warp: 2 ntg x 4 q) =======
    {
        uint32_t aV[8][4];
        const float* VMh = g_VM + h * 64 * STR;
        #pragma unroll
        for (int kk = 0; kk < 8; ++kk) {
            const int c0 = kk * 8 + tig;
            aV[kk][0] = __float_as_uint(VMh[r0 * STR + c0]);
            aV[kk][1] = __float_as_uint(VMh[(r0 + 8) * STR + c0]);
            aV[kk][2] = __float_as_uint(VMh[r0 * STR + c0 + 4]);
            aV[kk][3] = __float_as_uint(VMh[(r0 + 8) * STR + c0 + 4]);
        }
        for (int ntg = 0; ntg < 2; ++ntg) {
            float acc[4][4];
            #pragma unroll
            for (int q = 0; q < 4; ++q)
                acc[q][0] = acc[q][1] = acc[q][2] = acc[q][3] = 0.0f;
            #pragma unroll
            for (int kk = 0; kk < 8; ++kk) {
                #pragma unroll
                for (int q = 0; q < 4; ++q) {
                    const int c0 = nhalf * 64 + (ntg * 4 + q) * 8;
                    const uint32_t b0 = __float_as_uint(
                        u_s[(c0 + gid) * STR + kk * 8 + tig]);
                    const uint32_t b1 = __float_as_uint(
                        u_s[(c0 + gid) * STR + kk * 8 + tig + 4]);
                    mma_tf32(acc[q][0], acc[q][1], acc[q][2], acc[q][3],
                             aV[kk], b0, b1);
                }
            }
            #pragma unroll
            for (int q = 0; q < 4; ++q) {
                const int c0 = nhalf * 64 + (ntg * 4 + q) * 8;
                const int cc = c0 + 2 * tig;
                vx_s[cc * STR + r0]           = acc[q][0];
                vx_s[(cc + 1) * STR + r0]     = acc[q][1];
                vx_s[cc * STR + r0 + 8]       = acc[q][2];
                vx_s[(cc + 1) * STR + r0 + 8] = acc[q][3];
            }
        }
    }
    __syncthreads();

    // ---- prefetch Toeplitz A-fragments (overlaps with the scan below) ----
    uint32_t aT[8][4];
    {
        const float* Th = g_T + h * 64 * STR;
        #pragma unroll
        for (int kk = 0; kk < 8; ++kk) {
            const int c0 = kk * 8 + tig;
            aT[kk][0] = __float_as_uint(Th[r0 * STR + c0]);
            aT[kk][1] = __float_as_uint(Th[(r0 + 8) * STR + c0]);
            aT[kk][2] = __float_as_uint(Th[r0 * STR + c0 + 4]);
            aT[kk][3] = __float_as_uint(Th[(r0 + 8) * STR + c0 + 4]);
        }
    }

    // ========== parallel scan: 8 segments x 16 chunks ====================
    const float w64r = g_w64r[h * N2 + lane];
    const float w64i = g_w64i[h * N2 + lane];
    const int sb = warp * 16;
    {
        // local scan from zero state; store unrounded pre-states
        float xr = 0.0f, xi = 0.0f;
        for (int c = sb; c < sb + 16; ++c) {
            const float vr = vx_s[c * STR + lane];
            const float vi = vx_s[c * STR + N2 + lane];
            vx_s[c * STR + lane]      = xr;
            vx_s[c * STR + N2 + lane] = xi;
            const float nxr = fmaf(w64r, xr, fmaf(-w64i, xi, vr));
            xi = fmaf(w64i, xr, fmaf(w64r, xi, vi));
            xr = nxr;
        }
        seg_s[warp * 136 + lane]      = xr;   // segment total T_w
        seg_s[warp * 136 + 32 + lane] = xi;
    }
    __syncthreads();

    if (warp == 0) {
        // q = w64^16 by 4 squarings
        float qr = w64r, qi = w64i;
        #pragma unroll
        for (int s2 = 0; s2 < 4; ++s2) {
            const float nr = qr * qr - qi * qi;
            qi = 2.0f * qr * qi;
            qr = nr;
        }
        float pr = 0.0f, pi = 0.0f;           // P_0 = 0
        for (int w = 0; w < 8; ++w) {
            seg_s[w * 136 + 68 + lane]  = pr;
            seg_s[w * 136 + 100 + lane] = pi;
            if (w < 7) {
                const float tr2 = seg_s[w * 136 + lane];
                const float ti2 = seg_s[w * 136 + 32 + lane];
                const float nr = fmaf(qr, pr, fmaf(-qi, pi, tr2));
                pi = fmaf(qi, pr, fmaf(qr, pi, ti2));
                pr = nr;
            }
        }
    }
    __syncthreads();

    {
        // correction: X[c] = tf32r(Xl[c] + p), p <- w64 * p
        float pr = seg_s[warp * 136 + 68 + lane];
        float pi = seg_s[warp * 136 + 100 + lane];
        for (int c = sb; c < sb + 16; ++c) {
            vx_s[c * STR + lane]      = tf32r(vx_s[c * STR + lane] + pr);
            vx_s[c * STR + N2 + lane] = tf32r(vx_s[c * STR + N2 + lane] + pi);
            const float nr = pr * w64r - pi * w64i;
            pi = fmaf(pr, w64i, pi * w64r);
            pr = nr;
        }
    }
    __syncthreads();

    // ====== Y GEMM: Y = T @ U + PM @ X, epilogue += D*u ==================
    {
        uint32_t aP[8][4];
        const float* PMh = g_PM + h * 64 * STR;
        #pragma unroll
        for (int kk = 0; kk < 8; ++kk) {
            const int c0 = kk * 8 + tig;
            aP[kk][0] = __float_as_uint(PMh[r0 * STR + c0]);
            aP[kk][1] = __float_as_uint(PMh[(r0 + 8) * STR + c0]);
            aP[kk][2] = __float_as_uint(PMh[r0 * STR + c0 + 4]);
            aP[kk][3] = __float_as_uint(PMh[(r0 + 8) * STR + c0 + 4]);
        }
        const float d = Dv[h];

        for (int ntg = 0; ntg < 2; ++ntg) {
            float acc[4][4];
            #pragma unroll
            for (int q = 0; q < 4; ++q)
                acc[q][0] = acc[q][1] = acc[q][2] = acc[q][3] = 0.0f;
            #pragma unroll
            for (int kk = 0; kk < 8; ++kk) {
                #pragma unroll
                for (int q = 0; q < 4; ++q) {
                    const int c0 = nhalf * 64 + (ntg * 4 + q) * 8;
                    const uint32_t b0 = __float_as_uint(
                        u_s[(c0 + gid) * STR + kk * 8 + tig]);
                    const uint32_t b1 = __float_as_uint(
                        u_s[(c0 + gid) * STR + kk * 8 + tig + 4]);
                    mma_tf32(acc[q][0], acc[q][1], acc[q][2], acc[q][3],
                             aT[kk], b0, b1);
                }
            }
            #pragma unroll
            for (int kk = 0; kk < 8; ++kk) {
                #pragma unroll
                for (int q = 0; q < 4; ++q) {
                    const int c0 = nhalf * 64 + (ntg * 4 + q) * 8;
                    const uint32_t b0 = __float_as_uint(
                        vx_s[(c0 + gid) * STR + kk * 8 + tig]);
                    const uint32_t b1 = __float_as_uint(
                        vx_s[(c0 + gid) * STR + kk * 8 + tig + 4]);
                    mma_tf32(acc[q][0], acc[q][1], acc[q][2], acc[q][3],
                             aP[kk], b0, b1);
                }
            }
            #pragma unroll
            for (int q = 0; q < 4; ++q) {
                const int c0 = nhalf * 64 + (ntg * 4 + q) * 8;
                const int cc = c0 + 2 * tig;
                yp[cc * LC + r0] =
                    fmaf(d, u_s[cc * STR + r0], acc[q][0]);
                yp[(cc + 1) * LC + r0] =
                    fmaf(d, u_s[(cc + 1) * STR + r0], acc[q][1]);
                yp[cc * LC + r0 + 8] =
                    fmaf(d, u_s[cc * STR + r0 + 8], acc[q][2]);
                yp[(cc + 1) * LC + r0 + 8] =
                    fmaf(d, u_s[(cc + 1) * STR + r0 + 8], acc[q][3]);
            }
        }
    }
}

// ============================== launch =================================
extern "C" void kernel_launch(void* const* d_in, const int* in_sizes, int n_in,
                              void* d_out, int out_size)
{
    const float* u          = (const float*)d_in[0];
    const float* log_dt     = (const float*)d_in[1];
    const float* log_A_real = (const float*)d_in[2];
    const float* A_imag     = (const float*)d_in[3];
    const float* C          = (const float*)d_in[4];
    const float* D          = (const float*)d_in[5];
    float* y = (float*)d_out;

    const int smem = (2 * NC * STR + 8 * 136) * (int)sizeof(float); // 73984 B
    cudaFuncSetAttribute(s4d_main,
                         cudaFuncAttributeMaxDynamicSharedMemorySize, smem);

    s4d_param<<<Hh, 128>>>(log_dt, log_A_real, A_imag, C);
    s4d_main<<<Bb * Hh, 256, smem>>>(u, D, y);
}

// round 11
// speedup vs baseline: 3.7125x; 1.2852x over previous
#include <cuda_runtime.h>
#include <cstdint>
#include <math.h>

// S4D via chunked state-passing + tf32 tensor cores. R11:
//  - warp tile = 2 M-tiles x 1 N-quarter  -> B-fragment smem traffic halved
//  - u_s / vx_s stored k-permuted (i -> 2(i&3)|(i>>2) within 8) so each mma B
//    pair is ONE LDS.64; STR=72 (== 8 mod 32) makes it bank-conflict-free
//  - A matrices (T, VM, PM) pre-written in mma fragment order by the param
//    kernel -> main loads A with coalesced LDG.128
//  - D folded into Toeplitz diagonal: no epilogue u_s reads

constexpr int Hh = 256;
constexpr int N2 = 32;
constexpr int Bb = 16;
constexpr int Ll = 8192;
constexpr int LC  = 64;
constexpr int NC  = 128;
constexpr int STR = 72;     // smem row stride in floats (8 mod 32)

// fragment-format matrices: [h][mtile(4)][kk(8)][lane(32)][reg(4)]
__device__ float g_Tf[Hh * 4 * 8 * 128];
__device__ float g_Vf[Hh * 4 * 8 * 128];
__device__ float g_Pf[Hh * 4 * 8 * 128];
__device__ float g_w64r[Hh * N2];
__device__ float g_w64i[Hh * N2];

__device__ __forceinline__ float tf32r(float x) {
    uint32_t u;
    asm("cvt.rna.tf32.f32 %0, %1;" : "=r"(u) : "f"(x));
    return __uint_as_float(u);
}

__device__ __forceinline__ void mma_tf32(float* d, const uint32_t a[4],
                                         uint32_t b0, uint32_t b1) {
    asm volatile(
        "mma.sync.aligned.m16n8k8.row.col.f32.tf32.tf32.f32 "
        "{%0,%1,%2,%3}, {%4,%5,%6,%7}, {%8,%9}, {%0,%1,%2,%3};"
        : "+f"(d[0]), "+f"(d[1]), "+f"(d[2]), "+f"(d[3])
        : "r"(a[0]), "r"(a[1]), "r"(a[2]), "r"(a[3]), "r"(b0), "r"(b1));
}

// ============================ param kernel =============================
__global__ __launch_bounds__(128, 8)
void s4d_param(const float* __restrict__ log_dt,
               const float* __restrict__ log_A_real,
               const float* __restrict__ A_imag,
               const float* __restrict__ C,
               const float* __restrict__ Dv)
{
    const int h = blockIdx.x;
    const int t = threadIdx.x;

    __shared__ float k_s[64];
    __shared__ float ctr_s[N2], cti_s[N2], dar_s[N2], dai_s[N2];

    if (t < N2) {
        const int n = t;
        const float dt = expf(log_dt[h]);
        const float ar = -expf(log_A_real[h * N2 + n]);
        const float ai = A_imag[h * N2 + n];
        const float dtar = ar * dt, dtai = ai * dt;
        const float na = ar * ar + ai * ai;
        const float mag = expf(dtar);
        const float wr = mag * cosf(dtai);
        const float wi = mag * sinf(dtai);
        const float tr = wr - 1.0f, ti = wi;
        const float qr = (tr * ar + ti * ai) / na;
        const float qi = (ti * ar - tr * ai) / na;
        const float cr = C[(h * N2 + n) * 2 + 0];
        const float ci = C[(h * N2 + n) * 2 + 1];
        ctr_s[n] = 2.0f * (cr * qr - ci * qi);
        cti_s[n] = 2.0f * (cr * qi + ci * qr);
        dar_s[n] = dtar;
        dai_s[n] = dtai;
        const float m64 = expf(64.0f * dtar);
        g_w64r[h * N2 + n] = m64 * cosf(64.0f * dtai);
        g_w64i[h * N2 + n] = m64 * sinf(64.0f * dtai);
    }
    __syncthreads();

    if (t < 64) {                       // k[m] = Re(sum_n Ct_n w_n^m)
        float sum = 0.0f;
        const float m = (float)t;
        for (int n = 0; n < N2; ++n) {
            const float e = expf(m * dar_s[n]);
            float sn, cs;
            sincosf(m * dai_s[n], &sn, &cs);
            sum += ctr_s[n] * (e * cs) - cti_s[n] * (e * sn);
        }
        k_s[t] = sum;
    }
    __syncthreads();

    const int warp = t >> 5;            // = mtile
    const int lane = t & 31;
    const int gid  = lane >> 2;
    const int tig  = lane & 3;
    const int mt   = warp;
    const int r0   = 16 * mt + gid;
    const float k0pD = k_s[0] + Dv[h];  // fold D into Toeplitz diagonal

    auto Tval = [&](int r, int c) -> float {
        if (c > r) return 0.0f;
        if (c == r) return tf32r(k0pD);
        return tf32r(k_s[r - c]);
    };
    auto Vval = [&](int r, int c) -> float {
        const int n = r & 31;
        const float e = (float)(63 - c);
        const float mg = expf(e * dar_s[n]);
        float sn, cs;
        sincosf(e * dai_s[n], &sn, &cs);
        return tf32r((r < 32) ? mg * cs : mg * sn);
    };
    auto Pval = [&](int r, int c) -> float {
        const int n = c & 31;
        const float p = (float)(r + 1);
        const float mg = expf(p * dar_s[n]);
        float sn, cs;
        sincosf(p * dai_s[n], &sn, &cs);
        const float wr = mg * cs, wi = mg * sn;
        const float zr = ctr_s[n] * wr - cti_s[n] * wi;
        const float zi = ctr_s[n] * wi + cti_s[n] * wr;
        return tf32r((c < 32) ? zr : -zi);
    };

    for (int kk = 0; kk < 8; ++kk) {
        const int c0 = kk * 8 + tig;
        const int idx = ((h * 4 + mt) * 8 + kk) * 32 + lane;
        float4 v;
        v.x = Tval(r0, c0);     v.y = Tval(r0 + 8, c0);
        v.z = Tval(r0, c0 + 4); v.w = Tval(r0 + 8, c0 + 4);
        reinterpret_cast<float4*>(g_Tf)[idx] = v;
        v.x = Vval(r0, c0);     v.y = Vval(r0 + 8, c0);
        v.z = Vval(r0, c0 + 4); v.w = Vval(r0 + 8, c0 + 4);
        reinterpret_cast<float4*>(g_Vf)[idx] = v;
        v.x = Pval(r0, c0);     v.y = Pval(r0 + 8, c0);
        v.z = Pval(r0, c0 + 4); v.w = Pval(r0 + 8, c0 + 4);
        reinterpret_cast<float4*>(g_Pf)[idx] = v;
    }
}

// ============================= main kernel =============================
__global__ __launch_bounds__(256, 2)
void s4d_main(const float* __restrict__ u, float* __restrict__ y)
{
    extern __shared__ float sh[];
    float* u_s   = sh;                    // [NC][STR] u, tf32, k-permuted
    float* vx_s  = sh + NC * STR;         // [NC][STR] V then X, k-permuted
    float* seg_s = sh + 2 * NC * STR;     // [8][136] scan segment state

    const int g = blockIdx.x;             // b*H + h
    const int h = g & (Hh - 1);
    const int tid   = threadIdx.x;
    const int warp  = tid >> 5;
    const int lane  = tid & 31;
    const int gid   = lane >> 2;
    const int tig   = lane & 3;
    const int mrow2 = warp >> 2;          // 0..1 : which M half (2 mtiles)
    const int nq    = warp & 3;           // 0..3 : which 32-chunk quarter

    const float* __restrict__ up = u + (size_t)g * Ll;
    float*       __restrict__ yp = y + (size_t)g * Ll;

    // ---- stage u: tf32-round + k-permute (within each 8: i->2(i&3)|(i>>2))
    {
        const float4* up4 = reinterpret_cast<const float4*>(up);
        for (int gi = tid; gi < Ll / 8; gi += 256) {
            const int c = gi >> 3, grp = gi & 7;
            const float4 a = up4[gi * 2];
            const float4 b = up4[gi * 2 + 1];
            float4 w0, w1;
            w0.x = tf32r(a.x); w0.y = tf32r(b.x);
            w0.z = tf32r(a.y); w0.w = tf32r(b.y);
            w1.x = tf32r(a.z); w1.y = tf32r(b.z);
            w1.z = tf32r(a.w); w1.w = tf32r(b.w);
            float* dst = &u_s[c * STR + grp * 8];
            reinterpret_cast<float4*>(dst)[0] = w0;
            reinterpret_cast<float4*>(dst)[1] = w1;
        }
    }
    __syncthreads();

    uint32_t aA[2][8][4];      // A fragments for this warp's 2 mtiles

    // ================= V GEMM: V = VM @ U =========
    {
        const float4* Vf4 = reinterpret_cast<const float4*>(g_Vf);
        #pragma unroll
        for (int mt2 = 0; mt2 < 2; ++mt2) {
            const int mt = mrow2 * 2 + mt2;
            #pragma unroll
            for (int kk = 0; kk < 8; ++kk) {
                const float4 v = Vf4[((h * 4 + mt) * 8 + kk) * 32 + lane];
                aA[mt2][kk][0] = __float_as_uint(v.x);
                aA[mt2][kk][1] = __float_as_uint(v.y);
                aA[mt2][kk][2] = __float_as_uint(v.z);
                aA[mt2][kk][3] = __float_as_uint(v.w);
            }
        }
        for (int nt = 0; nt < 4; ++nt) {
            const int nb = nq * 32 + nt * 8;        // chunk base
            float acc[2][4] = {};
            #pragma unroll
            for (int kk = 0; kk < 8; ++kk) {
                const float2 bb = *reinterpret_cast<const float2*>(
                    &u_s[(nb + gid) * STR + kk * 8 + 2 * tig]);
                const uint32_t b0 = __float_as_uint(bb.x);
                const uint32_t b1 = __float_as_uint(bb.y);
                mma_tf32(acc[0], aA[0][kk], b0, b1);
                mma_tf32(acc[1], aA[1][kk], b0, b1);
            }
            const int cc = nb + 2 * tig;
            #pragma unroll
            for (int mt2 = 0; mt2 < 2; ++mt2) {
                const int mb = 16 * (mrow2 * 2 + mt2);
                const int p0 = mb + ((gid & 3) << 1) + (gid >> 2); // perm row
                vx_s[cc * STR + p0]           = acc[mt2][0];
                vx_s[(cc + 1) * STR + p0]     = acc[mt2][1];
                vx_s[cc * STR + p0 + 8]       = acc[mt2][2];
                vx_s[(cc + 1) * STR + p0 + 8] = acc[mt2][3];
            }
        }
    }
    __syncthreads();

    // ---- prefetch Toeplitz fragments (overlaps the scan) ----
    {
        const float4* Tf4 = reinterpret_cast<const float4*>(g_Tf);
        #pragma unroll
        for (int mt2 = 0; mt2 < 2; ++mt2) {
            const int mt = mrow2 * 2 + mt2;
            #pragma unroll
            for (int kk = 0; kk < 8; ++kk) {
                const float4 v = Tf4[((h * 4 + mt) * 8 + kk) * 32 + lane];
                aA[mt2][kk][0] = __float_as_uint(v.x);
                aA[mt2][kk][1] = __float_as_uint(v.y);
                aA[mt2][kk][2] = __float_as_uint(v.z);
                aA[mt2][kk][3] = __float_as_uint(v.w);
            }
        }
    }

    // ========== parallel scan over chunk states (modes at permuted cols) ==
    const float w64r = g_w64r[h * N2 + lane];
    const float w64i = g_w64i[h * N2 + lane];
    const int pl = (lane & 24) | ((lane & 3) << 1) | ((lane >> 2) & 1);
    const int sb = warp * 16;
    {
        float xr = 0.0f, xi = 0.0f;
        for (int c = sb; c < sb + 16; ++c) {
            const float vr = vx_s[c * STR + pl];
            const float vi = vx_s[c * STR + 32 + pl];
            vx_s[c * STR + pl]      = xr;
            vx_s[c * STR + 32 + pl] = xi;
            const float nxr = fmaf(w64r, xr, fmaf(-w64i, xi, vr));
            xi = fmaf(w64i, xr, fmaf(w64r, xi, vi));
            xr = nxr;
        }
        seg_s[warp * 136 + lane]      = xr;
        seg_s[warp * 136 + 32 + lane] = xi;
    }
    __syncthreads();

    if (warp == 0) {
        float qr = w64r, qi = w64i;                   // q = w64^16
        #pragma unroll
        for (int s2 = 0; s2 < 4; ++s2) {
            const float nr = qr * qr - qi * qi;
            qi = 2.0f * qr * qi;
            qr = nr;
        }
        float pr = 0.0f, pi = 0.0f;
        for (int w = 0; w < 8; ++w) {
            seg_s[w * 136 + 68 + lane]  = pr;
            seg_s[w * 136 + 100 + lane] = pi;
            if (w < 7) {
                const float tr2 = seg_s[w * 136 + lane];
                const float ti2 = seg_s[w * 136 + 32 + lane];
                const float nr = fmaf(qr, pr, fmaf(-qi, pi, tr2));
                pi = fmaf(qi, pr, fmaf(qr, pi, ti2));
                pr = nr;
            }
        }
    }
    __syncthreads();

    {
        float pr = seg_s[warp * 136 + 68 + lane];
        float pi = seg_s[warp * 136 + 100 + lane];
        for (int c = sb; c < sb + 16; ++c) {
            vx_s[c * STR + pl]      = tf32r(vx_s[c * STR + pl] + pr);
            vx_s[c * STR + 32 + pl] = tf32r(vx_s[c * STR + 32 + pl] + pi);
            const float nr = pr * w64r - pi * w64i;
            pi = fmaf(pr, w64i, pi * w64r);
            pr = nr;
        }
    }
    __syncthreads();

    // ====== Y = T @ U + PM @ X (D folded into T diagonal) ================
    {
        float acc[2][4][4] = {};
        // T @ U  (aA already holds T fragments)
        for (int nt = 0; nt < 4; ++nt) {
            const int nb = nq * 32 + nt * 8;
            #pragma unroll
            for (int kk = 0; kk < 8; ++kk) {
                const float2 bb = *reinterpret_cast<const float2*>(
                    &u_s[(nb + gid) * STR + kk * 8 + 2 * tig]);
                const uint32_t b0 = __float_as_uint(bb.x);
                const uint32_t b1 = __float_as_uint(bb.y);
                mma_tf32(acc[0][nt], aA[0][kk], b0, b1);
                mma_tf32(acc[1][nt], aA[1][kk], b0, b1);
            }
        }
        // load PM fragments
        {
            const float4* Pf4 = reinterpret_cast<const float4*>(g_Pf);
            #pragma unroll
            for (int mt2 = 0; mt2 < 2; ++mt2) {
                const int mt = mrow2 * 2 + mt2;
                #pragma unroll
                for (int kk = 0; kk < 8; ++kk) {
                    const float4 v = Pf4[((h * 4 + mt) * 8 + kk) * 32 + lane];
                    aA[mt2][kk][0] = __float_as_uint(v.x);
                    aA[mt2][kk][1] = __float_as_uint(v.y);
                    aA[mt2][kk][2] = __float_as_uint(v.z);
                    aA[mt2][kk][3] = __float_as_uint(v.w);
                }
            }
        }
        // PM @ X
        for (int nt = 0; nt < 4; ++nt) {
            const int nb = nq * 32 + nt * 8;
            #pragma unroll
            for (int kk = 0; kk < 8; ++kk) {
                const float2 bb = *reinterpret_cast<const float2*>(
                    &vx_s[(nb + gid) * STR + kk * 8 + 2 * tig]);
                const uint32_t b0 = __float_as_uint(bb.x);
                const uint32_t b1 = __float_as_uint(bb.y);
                mma_tf32(acc[0][nt], aA[0][kk], b0, b1);
                mma_tf32(acc[1][nt], aA[1][kk], b0, b1);
            }
        }
        // epilogue: direct STG (y[l] = y[c*64 + i])
        #pragma unroll
        for (int mt2 = 0; mt2 < 2; ++mt2) {
            const int r0 = 16 * (mrow2 * 2 + mt2) + gid;
            #pragma unroll
            for (int nt = 0; nt < 4; ++nt) {
                const int cc = nq * 32 + nt * 8 + 2 * tig;
                yp[cc * LC + r0]           = acc[mt2][nt][0];
                yp[(cc + 1) * LC + r0]     = acc[mt2][nt][1];
                yp[cc * LC + r0 + 8]       = acc[mt2][nt][2];
                yp[(cc + 1) * LC + r0 + 8] = acc[mt2][nt][3];
            }
        }
    }
}

// ============================== launch =================================
extern "C" void kernel_launch(void* const* d_in, const int* in_sizes, int n_in,
                              void* d_out, int out_size)
{
    const float* u          = (const float*)d_in[0];
    const float* log_dt     = (const float*)d_in[1];
    const float* log_A_real = (const float*)d_in[2];
    const float* A_imag     = (const float*)d_in[3];
    const float* C          = (const float*)d_in[4];
    const float* D          = (const float*)d_in[5];
    float* y = (float*)d_out;

    const int smem = (2 * NC * STR + 8 * 136) * (int)sizeof(float); // 78080 B
    cudaFuncSetAttribute(s4d_main,
                         cudaFuncAttributeMaxDynamicSharedMemorySize, smem);

    s4d_param<<<Hh, 128>>>(log_dt, log_A_real, A_imag, C, D);
    s4d_main<<<Bb * Hh, 256, smem>>>(u, y);
}

// round 12
// speedup vs baseline: 3.9183x; 1.0554x over previous
#include <cuda_runtime.h>
#include <cstdint>
#include <math.h>

// S4D via chunked state-passing + tf32 tensor cores. R12:
//  - V GEMM and T@U fused in one kk-loop sharing every u B-fragment LDS.64
//  - scan keeps local pre-states in registers (vx: 1 read of V, 1 write of X)
//  - param kernel at 256 threads (warps split the kk range)

constexpr int Hh = 256;
constexpr int N2 = 32;
constexpr int Bb = 16;
constexpr int Ll = 8192;
constexpr int LC  = 64;
constexpr int NC  = 128;
constexpr int STR = 72;     // smem row stride (8 mod 32: conflict-free LDS.64)

// fragment-format matrices: [h][mtile(4)][kk(8)][lane(32)][reg(4)]
__device__ float g_Tf[Hh * 4 * 8 * 128];
__device__ float g_Vf[Hh * 4 * 8 * 128];
__device__ float g_Pf[Hh * 4 * 8 * 128];
__device__ float g_w64r[Hh * N2];
__device__ float g_w64i[Hh * N2];

__device__ __forceinline__ float tf32r(float x) {
    uint32_t u;
    asm("cvt.rna.tf32.f32 %0, %1;" : "=r"(u) : "f"(x));
    return __uint_as_float(u);
}

__device__ __forceinline__ void mma_tf32(float* d, const uint32_t a[4],
                                         uint32_t b0, uint32_t b1) {
    asm volatile(
        "mma.sync.aligned.m16n8k8.row.col.f32.tf32.tf32.f32 "
        "{%0,%1,%2,%3}, {%4,%5,%6,%7}, {%8,%9}, {%0,%1,%2,%3};"
        : "+f"(d[0]), "+f"(d[1]), "+f"(d[2]), "+f"(d[3])
        : "r"(a[0]), "r"(a[1]), "r"(a[2]), "r"(a[3]), "r"(b0), "r"(b1));
}

// ============================ param kernel =============================
__global__ __launch_bounds__(256, 4)
void s4d_param(const float* __restrict__ log_dt,
               const float* __restrict__ log_A_real,
               const float* __restrict__ A_imag,
               const float* __restrict__ C,
               const float* __restrict__ Dv)
{
    const int h = blockIdx.x;
    const int t = threadIdx.x;

    __shared__ float k_s[64];
    __shared__ float ctr_s[N2], cti_s[N2], dar_s[N2], dai_s[N2];

    if (t < N2) {
        const int n = t;
        const float dt = expf(log_dt[h]);
        const float ar = -expf(log_A_real[h * N2 + n]);
        const float ai = A_imag[h * N2 + n];
        const float dtar = ar * dt, dtai = ai * dt;
        const float na = ar * ar + ai * ai;
        const float mag = expf(dtar);
        const float wr = mag * cosf(dtai);
        const float wi = mag * sinf(dtai);
        const float tr = wr - 1.0f, ti = wi;
        const float qr = (tr * ar + ti * ai) / na;
        const float qi = (ti * ar - tr * ai) / na;
        const float cr = C[(h * N2 + n) * 2 + 0];
        const float ci = C[(h * N2 + n) * 2 + 1];
        ctr_s[n] = 2.0f * (cr * qr - ci * qi);
        cti_s[n] = 2.0f * (cr * qi + ci * qr);
        dar_s[n] = dtar;
        dai_s[n] = dtai;
        const float m64 = expf(64.0f * dtar);
        g_w64r[h * N2 + n] = m64 * cosf(64.0f * dtai);
        g_w64i[h * N2 + n] = m64 * sinf(64.0f * dtai);
    }
    __syncthreads();

    if (t < 64) {                       // k[m] = Re(sum_n Ct_n w_n^m)
        float sum = 0.0f;
        const float m = (float)t;
        for (int n = 0; n < N2; ++n) {
            const float e = expf(m * dar_s[n]);
            float sn, cs;
            sincosf(m * dai_s[n], &sn, &cs);
            sum += ctr_s[n] * (e * cs) - cti_s[n] * (e * sn);
        }
        k_s[t] = sum;
    }
    __syncthreads();

    const int warp = t >> 5;
    const int lane = t & 31;
    const int gid  = lane >> 2;
    const int tig  = lane & 3;
    const int mt   = warp & 3;
    const int kk0  = (warp >> 2) * 4;   // warps split the kk range
    const int r0   = 16 * mt + gid;
    const float k0pD = k_s[0] + Dv[h];

    auto Tval = [&](int r, int c) -> float {
        if (c > r) return 0.0f;
        if (c == r) return tf32r(k0pD);
        return tf32r(k_s[r - c]);
    };
    auto Vval = [&](int r, int c) -> float {
        const int n = r & 31;
        const float e = (float)(63 - c);
        const float mg = expf(e * dar_s[n]);
        float sn, cs;
        sincosf(e * dai_s[n], &sn, &cs);
        return tf32r((r < 32) ? mg * cs : mg * sn);
    };
    auto Pval = [&](int r, int c) -> float {
        const int n = c & 31;
        const float p = (float)(r + 1);
        const float mg = expf(p * dar_s[n]);
        float sn, cs;
        sincosf(p * dai_s[n], &sn, &cs);
        const float wr = mg * cs, wi = mg * sn;
        const float zr = ctr_s[n] * wr - cti_s[n] * wi;
        const float zi = ctr_s[n] * wi + cti_s[n] * wr;
        return tf32r((c < 32) ? zr : -zi);
    };

    for (int kk = kk0; kk < kk0 + 4; ++kk) {
        const int c0 = kk * 8 + tig;
        const int idx = ((h * 4 + mt) * 8 + kk) * 32 + lane;
        float4 v;
        v.x = Tval(r0, c0);     v.y = Tval(r0 + 8, c0);
        v.z = Tval(r0, c0 + 4); v.w = Tval(r0 + 8, c0 + 4);
        reinterpret_cast<float4*>(g_Tf)[idx] = v;
        v.x = Vval(r0, c0);     v.y = Vval(r0 + 8, c0);
        v.z = Vval(r0, c0 + 4); v.w = Vval(r0 + 8, c0 + 4);
        reinterpret_cast<float4*>(g_Vf)[idx] = v;
        v.x = Pval(r0, c0);     v.y = Pval(r0 + 8, c0);
        v.z = Pval(r0, c0 + 4); v.w = Pval(r0 + 8, c0 + 4);
        reinterpret_cast<float4*>(g_Pf)[idx] = v;
    }
}

// ============================= main kernel =============================
__global__ __launch_bounds__(256, 2)
void s4d_main(const float* __restrict__ u, float* __restrict__ y)
{
    extern __shared__ float sh[];
    float* u_s   = sh;                    // [NC][STR] u, tf32, k-permuted
    float* vx_s  = sh + NC * STR;         // [NC][STR] V then X, k-permuted
    float* seg_s = sh + 2 * NC * STR;     // [8][136] scan segment state

    const int g = blockIdx.x;             // b*H + h
    const int h = g & (Hh - 1);
    const int tid   = threadIdx.x;
    const int warp  = tid >> 5;
    const int lane  = tid & 31;
    const int gid   = lane >> 2;
    const int tig   = lane & 3;
    const int mrow2 = warp >> 2;          // 0..1 : which M half (2 mtiles)
    const int nq    = warp & 3;           // 0..3 : which 32-chunk quarter

    const float* __restrict__ up = u + (size_t)g * Ll;
    float*       __restrict__ yp = y + (size_t)g * Ll;

    // ---- stage u: tf32-round + k-permute (within each 8: i->2(i&3)|(i>>2))
    {
        const float4* up4 = reinterpret_cast<const float4*>(up);
        for (int gi = tid; gi < Ll / 8; gi += 256) {
            const int c = gi >> 3, grp = gi & 7;
            const float4 a = up4[gi * 2];
            const float4 b = up4[gi * 2 + 1];
            float4 w0, w1;
            w0.x = tf32r(a.x); w0.y = tf32r(b.x);
            w0.z = tf32r(a.y); w0.w = tf32r(b.y);
            w1.x = tf32r(a.z); w1.y = tf32r(b.z);
            w1.z = tf32r(a.w); w1.w = tf32r(b.w);
            float* dst = &u_s[c * STR + grp * 8];
            reinterpret_cast<float4*>(dst)[0] = w0;
            reinterpret_cast<float4*>(dst)[1] = w1;
        }
    }
    __syncthreads();

    float accY[2][4][4] = {};      // T@U accumulators (live through scan)

    // ======== fused pass: V = VM @ U  and  accY = T @ U (shared B) =======
    {
        float accV[2][4][4] = {};
        const float4* Vf4 = reinterpret_cast<const float4*>(g_Vf);
        const float4* Tf4 = reinterpret_cast<const float4*>(g_Tf);

        #pragma unroll
        for (int kk = 0; kk < 8; ++kk) {
            uint32_t aV2[2][4], aT2[2][4];
            #pragma unroll
            for (int mt2 = 0; mt2 < 2; ++mt2) {
                const int mt = mrow2 * 2 + mt2;
                const float4 v = Vf4[((h * 4 + mt) * 8 + kk) * 32 + lane];
                aV2[mt2][0] = __float_as_uint(v.x);
                aV2[mt2][1] = __float_as_uint(v.y);
                aV2[mt2][2] = __float_as_uint(v.z);
                aV2[mt2][3] = __float_as_uint(v.w);
                const float4 w = Tf4[((h * 4 + mt) * 8 + kk) * 32 + lane];
                aT2[mt2][0] = __float_as_uint(w.x);
                aT2[mt2][1] = __float_as_uint(w.y);
                aT2[mt2][2] = __float_as_uint(w.z);
                aT2[mt2][3] = __float_as_uint(w.w);
            }
            #pragma unroll
            for (int nt = 0; nt < 4; ++nt) {
                const int nb = nq * 32 + nt * 8;
                const float2 bb = *reinterpret_cast<const float2*>(
                    &u_s[(nb + gid) * STR + kk * 8 + 2 * tig]);
                const uint32_t b0 = __float_as_uint(bb.x);
                const uint32_t b1 = __float_as_uint(bb.y);
                mma_tf32(accV[0][nt], aV2[0], b0, b1);
                mma_tf32(accV[1][nt], aV2[1], b0, b1);
                mma_tf32(accY[0][nt], aT2[0], b0, b1);
                mma_tf32(accY[1][nt], aT2[1], b0, b1);
            }
        }
        // store V
        #pragma unroll
        for (int nt = 0; nt < 4; ++nt) {
            const int cc = nq * 32 + nt * 8 + 2 * tig;
            #pragma unroll
            for (int mt2 = 0; mt2 < 2; ++mt2) {
                const int mb = 16 * (mrow2 * 2 + mt2);
                const int p0 = mb + ((gid & 3) << 1) + (gid >> 2);
                vx_s[cc * STR + p0]           = accV[mt2][nt][0];
                vx_s[(cc + 1) * STR + p0]     = accV[mt2][nt][1];
                vx_s[cc * STR + p0 + 8]       = accV[mt2][nt][2];
                vx_s[(cc + 1) * STR + p0 + 8] = accV[mt2][nt][3];
            }
        }
    }
    __syncthreads();

    // ========== parallel scan; local pre-states kept in registers ========
    const float w64r = g_w64r[h * N2 + lane];
    const float w64i = g_w64i[h * N2 + lane];
    const int pl = (lane & 24) | ((lane & 3) << 1) | ((lane >> 2) & 1);
    const int sb = warp * 16;
    float sxr[16], sxi[16];
    {
        float xr = 0.0f, xi = 0.0f;
        #pragma unroll
        for (int cc = 0; cc < 16; ++cc) {
            const int c = sb + cc;
            const float vr = vx_s[c * STR + pl];
            const float vi = vx_s[c * STR + 32 + pl];
            sxr[cc] = xr;
            sxi[cc] = xi;
            const float nxr = fmaf(w64r, xr, fmaf(-w64i, xi, vr));
            xi = fmaf(w64i, xr, fmaf(w64r, xi, vi));
            xr = nxr;
        }
        seg_s[warp * 136 + lane]      = xr;
        seg_s[warp * 136 + 32 + lane] = xi;
    }
    __syncthreads();

    if (warp == 0) {
        float qr = w64r, qi = w64i;                   // q = w64^16
        #pragma unroll
        for (int s2 = 0; s2 < 4; ++s2) {
            const float nr = qr * qr - qi * qi;
            qi = 2.0f * qr * qi;
            qr = nr;
        }
        float pr = 0.0f, pi = 0.0f;
        for (int w = 0; w < 8; ++w) {
            seg_s[w * 136 + 68 + lane]  = pr;
            seg_s[w * 136 + 100 + lane] = pi;
            if (w < 7) {
                const float tr2 = seg_s[w * 136 + lane];
                const float ti2 = seg_s[w * 136 + 32 + lane];
                const float nr = fmaf(qr, pr, fmaf(-qi, pi, tr2));
                pi = fmaf(qi, pr, fmaf(qr, pi, ti2));
                pr = nr;
            }
        }
    }
    __syncthreads();

    {
        float pr = seg_s[warp * 136 + 68 + lane];
        float pi = seg_s[warp * 136 + 100 + lane];
        #pragma unroll
        for (int cc = 0; cc < 16; ++cc) {
            const int c = sb + cc;
            vx_s[c * STR + pl]      = tf32r(sxr[cc] + pr);
            vx_s[c * STR + 32 + pl] = tf32r(sxi[cc] + pi);
            const float nr = pr * w64r - pi * w64i;
            pi = fmaf(pr, w64i, pi * w64r);
            pr = nr;
        }
    }
    __syncthreads();

    // ====== accY += PM @ X, then epilogue store ==========================
    {
        const float4* Pf4 = reinterpret_cast<const float4*>(g_Pf);
        #pragma unroll
        for (int kk = 0; kk < 8; ++kk) {
            uint32_t aP2[2][4];
            #pragma unroll
            for (int mt2 = 0; mt2 < 2; ++mt2) {
                const int mt = mrow2 * 2 + mt2;
                const float4 v = Pf4[((h * 4 + mt) * 8 + kk) * 32 + lane];
                aP2[mt2][0] = __float_as_uint(v.x);
                aP2[mt2][1] = __float_as_uint(v.y);
                aP2[mt2][2] = __float_as_uint(v.z);
                aP2[mt2][3] = __float_as_uint(v.w);
            }
            #pragma unroll
            for (int nt = 0; nt < 4; ++nt) {
                const int nb = nq * 32 + nt * 8;
                const float2 bb = *reinterpret_cast<const float2*>(
                    &vx_s[(nb + gid) * STR + kk * 8 + 2 * tig]);
                const uint32_t b0 = __float_as_uint(bb.x);
                const uint32_t b1 = __float_as_uint(bb.y);
                mma_tf32(accY[0][nt], aP2[0], b0, b1);
                mma_tf32(accY[1][nt], aP2[1], b0, b1);
            }
        }
        #pragma unroll
        for (int mt2 = 0; mt2 < 2; ++mt2) {
            const int r0 = 16 * (mrow2 * 2 + mt2) + gid;
            #pragma unroll
            for (int nt = 0; nt < 4; ++nt) {
                const int cc = nq * 32 + nt * 8 + 2 * tig;
                yp[cc * LC + r0]           = accY[mt2][nt][0];
                yp[(cc + 1) * LC + r0]     = accY[mt2][nt][1];
                yp[cc * LC + r0 + 8]       = accY[mt2][nt][2];
                yp[(cc + 1) * LC + r0 + 8] = accY[mt2][nt][3];
            }
        }
    }
}

// ============================== launch =================================
extern "C" void kernel_launch(void* const* d_in, const int* in_sizes, int n_in,
                              void* d_out, int out_size)
{
    const float* u          = (const float*)d_in[0];
    const float* log_dt     = (const float*)d_in[1];
    const float* log_A_real = (const float*)d_in[2];
    const float* A_imag     = (const float*)d_in[3];
    const float* C          = (const float*)d_in[4];
    const float* D          = (const float*)d_in[5];
    float* y = (float*)d_out;

    const int smem = (2 * NC * STR + 8 * 136) * (int)sizeof(float); // 78080 B
    cudaFuncSetAttribute(s4d_main,
                         cudaFuncAttributeMaxDynamicSharedMemorySize, smem);

    s4d_param<<<Hh, 256>>>(log_dt, log_A_real, A_imag, C, D);
    s4d_main<<<Bb * Hh, 256, smem>>>(u, y);
}